// round 16
// baseline (speedup 1.0000x reference)
#include <cuda_runtime.h>
#include <cuda_fp16.h>
#include <cuda_bf16.h>

#define GSZ 8
#define DIMN 160
#define N3 (DIMN*DIMN*DIMN)
#define NLINE (4 * DIMN * DIMN)               // b * d * h lines

// Precomputed per-(b,d,h) x-node lerp pairs, split planes:
//   gA[line*8+i] = (c0: g[i], g[i+1]) , (c1: g[i], g[i+1])   -> one LDG.128
//   gB[line*8+i] = (c2: g[i], g[i+1])                        -> one LDG.64
__device__ float4 gA[NLINE * GSZ];            // 13.1 MB
__device__ float2 gB[NLINE * GSZ];            // 6.55 MB

// x-pair-packed fp16 mirror: xp[b*N3+v] = ( h2(ch0[v],ch1[v]), h2(ch0[v+1],ch1[v+1]) )
// .y of a row-tail voxel is from the next row but always carries weight ax=0.
__device__ uint2 xp[4 * N3 + 4];              // 131 MB (+pad)

// ---- prepass 1: interleave + fp16 convert + x-pair pack (pure streaming) ----
// thread = 4 consecutive voxels of one batch. grid (N3/1024, 4), block 256.
__global__ void __launch_bounds__(256) interleave_kernel(
    const float* __restrict__ x)              // [B,2,160,160,160]
{
    const int b = blockIdx.y;
    const int v = (blockIdx.x * 256 + threadIdx.x) * 4;
    const float* xb = x + (size_t)b * 2 * N3;
    const float4 a = *(const float4*)(xb + v);        // ch0 [v..v+3]
    const float4 c = *(const float4*)(xb + N3 + v);   // ch1 [v..v+3]
    const int vn = min(v + 4, N3 - 1);                // clamped neighbor (tail only)
    const float a4 = xb[vn];
    const float c4 = xb[N3 + vn];

    __half2 h0 = __floats2half2_rn(a.x, c.x);
    __half2 h1 = __floats2half2_rn(a.y, c.y);
    __half2 h2 = __floats2half2_rn(a.z, c.z);
    __half2 h3 = __floats2half2_rn(a.w, c.w);
    __half2 h4 = __floats2half2_rn(a4, c4);

    const unsigned u0 = *(unsigned*)&h0, u1 = *(unsigned*)&h1;
    const unsigned u2 = *(unsigned*)&h2, u3 = *(unsigned*)&h3;
    const unsigned u4 = *(unsigned*)&h4;

    uint4 q0, q1;
    q0.x = u0; q0.y = u1;  q0.z = u1; q0.w = u2;      // pairs (v),(v+1)
    q1.x = u2; q1.y = u3;  q1.z = u3; q1.w = u4;      // pairs (v+2),(v+3)
    uint4* dst = (uint4*)(xp + (size_t)b * N3 + v);
    dst[0] = q0;
    dst[1] = q1;
}

// ---- prepass 2: coarse-flow x-node pairs (unchanged) ----
__global__ void __launch_bounds__(256) flow_nodes_kernel(
    const float* __restrict__ flow)           // [B,3,8,8,8]
{
    const int tid  = threadIdx.x;
    const int node = tid & 7;
    const int hl   = tid >> 3;
    const int h    = blockIdx.x * 32 + hl;
    const int d    = blockIdx.y;
    const int b    = blockIdx.z;

    const float s = 7.0f / 159.0f;
    const float cz = d * s, cy = h * s;
    const int   iz0 = (int)cz, iy0 = (int)cy;
    const float fz = cz - iz0, fy = cy - iy0;
    const int   iz1 = min(iz0 + 1, GSZ - 1);
    const int   iy1 = min(iy0 + 1, GSZ - 1);

    const int r00 = (iz0 * GSZ + iy0) * GSZ + node;
    const int r01 = (iz0 * GSZ + iy1) * GSZ + node;
    const int r10 = (iz1 * GSZ + iy0) * GSZ + node;
    const int r11 = (iz1 * GSZ + iy1) * GSZ + node;

    float gi[3];
    #pragma unroll
    for (int c = 0; c < 3; c++) {
        const float* fb = flow + (((size_t)b * 3 + c) << 9);   // *512
        const float a0 = __ldg(fb + r00);
        const float a1 = __ldg(fb + r01);
        const float a2 = __ldg(fb + r10);
        const float a3 = __ldg(fb + r11);
        const float v0 = a0 + fy * (a1 - a0);
        const float v1 = a2 + fy * (a3 - a2);
        gi[c] = v0 + fz * (v1 - v0);
    }

    float gn[3];
    #pragma unroll
    for (int c = 0; c < 3; c++) {
        const float nb = __shfl_down_sync(0xffffffffu, gi[c], 1);
        gn[c] = (node == 7) ? gi[c] : nb;
    }

    const size_t line8 = (((size_t)b * DIMN + d) * DIMN + h) * GSZ + node;
    float4 qa; qa.x = gi[0]; qa.y = gn[0]; qa.z = gi[1]; qa.w = gn[1];
    float2 qb; qb.x = gi[2]; qb.y = gn[2];
    gA[line8] = qa;
    gB[line8] = qb;
}

__device__ __forceinline__ float reflect1(float c) {
    // mirror, period 2*(n-1)=318; single fold valid since |delta| <= ~16
    c = fabsf(c);
    return (c > 159.0f) ? (318.0f - c) : c;
}

// Per-voxel setup: base offset, y/z steps, 4 row weights + (bx0, ax).
__device__ __forceinline__ void voxel_setup(
    int b, int d, int h, int w, int ix0, float fx,
    int& base, int& dy, int& dz, float* wr, float& bx0, float& ax)
{
    const size_t line8 = (((size_t)b * DIMN + d) * DIMN + h) * GSZ + ix0;
    const float4 qa = __ldg(gA + line8);
    const float2 qb = __ldg(gB + line8);
    const float upx = qa.x + fx * (qa.y - qa.x);
    const float upy = qa.z + fx * (qa.w - qa.z);
    const float upz = qb.x + fx * (qb.y - qb.x);

    const float px = reflect1((float)w + upx * 79.5f);
    const float py = reflect1((float)h + upy * 79.5f);
    const float pz = reflect1((float)d + upz * 79.5f);

    const int jx0 = (int)px;
    const int jy0 = (int)py;
    const int jz0 = (int)pz;
    ax = px - (float)jx0;        // == 0 when jx0 == 159 -> pair .y weight 0
    const float ay = py - (float)jy0;
    const float az = pz - (float)jz0;
    bx0 = 1.0f - ax;

    dy = (jy0 < DIMN - 1) ? DIMN      : 0;
    dz = (jz0 < DIMN - 1) ? DIMN*DIMN : 0;
    base = (jz0 * DIMN + jy0) * DIMN + jx0;

    const float by0 = 1.0f - ay, bz0 = 1.0f - az;
    wr[0] = bz0 * by0;  wr[1] = bz0 * ay;
    wr[2] = az  * by0;  wr[3] = az  * ay;
}

__global__ void __launch_bounds__(256) elastic_kernel(
    float* __restrict__ out)           // [B,2,160,160,160]
{
    // block: 32 w x 8 ty, each thread does voxels (w, h) and (w, h+8).
    // grid: (5 w-tiles, 10 h-tiles * 160 d, 4 b)
    const int b  = blockIdx.z;
    const int d  = blockIdx.y / 10;
    const int ht = blockIdx.y % 10;
    const int tx = threadIdx.x;
    const int hA = ht * 16 + threadIdx.y;
    const int hB = hA + 8;
    const int w  = blockIdx.x * 32 + tx;

    // shared across both voxels (same w)
    const float s = 7.0f / 159.0f;
    const float cx  = w * s;
    const int   ix0 = (int)cx;
    const float fx  = cx - ix0;

    int baseA, dyA, dzA, baseB, dyB, dzB;
    float wrA[4], wrB[4], bx0A, axA, bx0B, axB;
    voxel_setup(b, d, hA, w, ix0, fx, baseA, dyA, dzA, wrA, bx0A, axA);
    voxel_setup(b, d, hB, w, ix0, fx, baseB, dyB, dzB, wrB, bx0B, axB);

    const uint2* __restrict__ xb = xp + (size_t)b * N3;

    // front-batch all 8 pair-loads (2 voxels x 4 rows; each = 2 x-taps x 2 ch)
    uint2 qA[4], qB[4];
    {
        const uint2* p0 = xb + baseA;
        const uint2* p2 = p0 + dzA;
        qA[0] = __ldg(p0);        qA[1] = __ldg(p0 + dyA);
        qA[2] = __ldg(p2);        qA[3] = __ldg(p2 + dyA);
    }
    {
        const uint2* p0 = xb + baseB;
        const uint2* p2 = p0 + dzB;
        qB[0] = __ldg(p0);        qB[1] = __ldg(p0 + dyB);
        qB[2] = __ldg(p2);        qB[3] = __ldg(p2 + dyB);
    }

    float vA0 = 0.f, vA1 = 0.f, vB0 = 0.f, vB1 = 0.f;
    #pragma unroll
    for (int k = 0; k < 4; k++) {
        const float2 a0 = __half22float2(*(const __half2*)&qA[k].x); // (ch0,ch1)@x0
        const float2 a1 = __half22float2(*(const __half2*)&qA[k].y); // (ch0,ch1)@x1
        vA0 = fmaf(wrA[k], fmaf(bx0A, a0.x, axA * a1.x), vA0);
        vA1 = fmaf(wrA[k], fmaf(bx0A, a0.y, axA * a1.y), vA1);
        const float2 b0 = __half22float2(*(const __half2*)&qB[k].x);
        const float2 b1 = __half22float2(*(const __half2*)&qB[k].y);
        vB0 = fmaf(wrB[k], fmaf(bx0B, b0.x, axB * b1.x), vB0);
        vB1 = fmaf(wrB[k], fmaf(bx0B, b0.y, axB * b1.y), vB1);
    }

    const int spatialA = (d * DIMN + hA) * DIMN + w;
    const int spatialB = spatialA + 8 * DIMN;
    float* __restrict__ o0 = out + (size_t)b * 2 * N3;
    o0[spatialA]      = vA0;
    o0[N3 + spatialA] = vA1;
    o0[spatialB]      = vB0;
    o0[N3 + spatialB] = vB1;
}

extern "C" void kernel_launch(void* const* d_in, const int* in_sizes, int n_in,
                              void* d_out, int out_size) {
    const float* x    = (const float*)d_in[0];
    const float* flow = (const float*)d_in[1];
    float* out        = (float*)d_out;

    dim3 iblock(256);
    dim3 igrid(N3 / 1024, 4);          // 4 voxels/thread
    interleave_kernel<<<igrid, iblock>>>(x);

    dim3 pblock(256);                  // 32 h-lines x 8 nodes
    dim3 pgrid(5, DIMN, 4);            // (h-tiles, d, b)
    flow_nodes_kernel<<<pgrid, pblock>>>(flow);

    dim3 block(32, 8);                 // 256 threads, 2 voxels each
    dim3 grid(5, 10 * DIMN, 4);        // (w-tiles, h-tiles*d, b)
    elastic_kernel<<<grid, block>>>(out);
}

// round 17
// speedup vs baseline: 1.1437x; 1.1437x over previous
#include <cuda_runtime.h>
#include <cuda_fp16.h>
#include <cuda_bf16.h>

#define GSZ 8
#define DIMN 160
#define N3 (DIMN*DIMN*DIMN)
#define NLINE (4 * DIMN * DIMN)               // b * d * h lines
#define PAD   (DIMN*DIMN + DIMN + 4)          // one z-plane + row of slack for weight-0 taps

// Precomputed per-(b,d,h) x-node lerp pairs, split planes:
//   gA[line*8+i] = (c0: g[i], g[i+1]) , (c1: g[i], g[i+1])   -> one LDG.128
//   gB[line*8+i] = (c2: g[i], g[i+1])                        -> one LDG.64
__device__ float4 gA[NLINE * GSZ];            // 13.1 MB
__device__ float2 gB[NLINE * GSZ];            // 6.55 MB

// Channel-interleaved fp16 mirror of x: xh[b][voxel] = (ch0, ch1).
// Zero-initialized pad absorbs weight-0 out-of-range taps.
__device__ __half2 xh[4 * N3 + PAD];          // 65.6 MB

// ---- fused prepass: interleave (grid.y<4) + coarse-flow nodes (grid.y==4) ----
__global__ void __launch_bounds__(256) prepass_kernel(
    const float* __restrict__ x,              // [B,2,160,160,160]
    const float* __restrict__ flow)           // [B,3,8,8,8]
{
    if (blockIdx.y < 4) {
        // interleave + fp16 convert: thread = 4 consecutive voxels of batch b
        const int b = blockIdx.y;
        const int v = (blockIdx.x * 256 + threadIdx.x) * 4;
        const float* xb = x + (size_t)b * 2 * N3;
        const float4 a = *(const float4*)(xb + v);        // ch0
        const float4 c = *(const float4*)(xb + N3 + v);   // ch1

        __half2 h0 = __floats2half2_rn(a.x, c.x);
        __half2 h1 = __floats2half2_rn(a.y, c.y);
        __half2 h2 = __floats2half2_rn(a.z, c.z);
        __half2 h3 = __floats2half2_rn(a.w, c.w);

        uint4 q;
        q.x = *(unsigned*)&h0;  q.y = *(unsigned*)&h1;
        q.z = *(unsigned*)&h2;  q.w = *(unsigned*)&h3;
        *(uint4*)(xh + (size_t)b * N3 + v) = q;
        return;
    }

    // coarse-flow x-node pairs: 3200 worker blocks out of this 4000-block slice
    const int bx = blockIdx.x;
    if (bx >= 3200) return;
    const int b     = bx / 800;               // 800 = 160 d * 5 h-tiles
    const int rest  = bx - b * 800;
    const int d     = rest / 5;
    const int htile = rest - d * 5;

    const int tid  = threadIdx.x;
    const int node = tid & 7;
    const int hl   = tid >> 3;
    const int h    = htile * 32 + hl;

    const float s = 7.0f / 159.0f;
    const float cz = d * s, cy = h * s;
    const int   iz0 = (int)cz, iy0 = (int)cy;
    const float fz = cz - iz0, fy = cy - iy0;
    const int   iz1 = min(iz0 + 1, GSZ - 1);
    const int   iy1 = min(iy0 + 1, GSZ - 1);

    const int r00 = (iz0 * GSZ + iy0) * GSZ + node;
    const int r01 = (iz0 * GSZ + iy1) * GSZ + node;
    const int r10 = (iz1 * GSZ + iy0) * GSZ + node;
    const int r11 = (iz1 * GSZ + iy1) * GSZ + node;

    float gi[3];
    #pragma unroll
    for (int c = 0; c < 3; c++) {
        const float* fb = flow + (((size_t)b * 3 + c) << 9);   // *512
        const float a0 = __ldg(fb + r00);
        const float a1 = __ldg(fb + r01);
        const float a2 = __ldg(fb + r10);
        const float a3 = __ldg(fb + r11);
        const float v0 = a0 + fy * (a1 - a0);
        const float v1 = a2 + fy * (a3 - a2);
        gi[c] = v0 + fz * (v1 - v0);
    }

    float gn[3];
    #pragma unroll
    for (int c = 0; c < 3; c++) {
        const float nb = __shfl_down_sync(0xffffffffu, gi[c], 1);
        gn[c] = (node == 7) ? gi[c] : nb;
    }

    const size_t line8 = (((size_t)b * DIMN + d) * DIMN + h) * GSZ + node;
    float4 qa; qa.x = gi[0]; qa.y = gn[0]; qa.z = gi[1]; qa.w = gn[1];
    float2 qb; qb.x = gi[2]; qb.y = gn[2];
    gA[line8] = qa;
    gB[line8] = qb;
}

__device__ __forceinline__ float reflect1(float c) {
    // mirror, period 2*(n-1)=318; single fold valid since |delta| <= ~16
    c = fabsf(c);
    return (c > 159.0f) ? (318.0f - c) : c;
}

// Per-voxel setup: base offset + 8 factorized weights. No edge selects:
// a clamped neighbor always carries weight exactly 0, so constant strides are safe.
__device__ __forceinline__ void voxel_setup(
    int b, int d, int h, int w, int ix0, float fx,
    int& base, float* tw)
{
    const size_t line8 = (((size_t)b * DIMN + d) * DIMN + h) * GSZ + ix0;
    const float4 qa = __ldg(gA + line8);
    const float2 qb = __ldg(gB + line8);
    const float upx = qa.x + fx * (qa.y - qa.x);
    const float upy = qa.z + fx * (qa.w - qa.z);
    const float upz = qb.x + fx * (qb.y - qb.x);

    const float px = reflect1((float)w + upx * 79.5f);
    const float py = reflect1((float)h + upy * 79.5f);
    const float pz = reflect1((float)d + upz * 79.5f);

    const int jx0 = (int)px;
    const int jy0 = (int)py;
    const int jz0 = (int)pz;
    const float ax = px - (float)jx0;    // 0 when jx0==159
    const float ay = py - (float)jy0;
    const float az = pz - (float)jz0;

    base = (jz0 * DIMN + jy0) * DIMN + jx0;

    const float bx0 = 1.0f - ax, by0 = 1.0f - ay, bz0 = 1.0f - az;
    const float w00 = bz0 * by0, w01 = bz0 * ay;
    const float w10 = az * by0,  w11 = az * ay;
    tw[0] = w00 * bx0;  tw[1] = w00 * ax;
    tw[2] = w01 * bx0;  tw[3] = w01 * ax;
    tw[4] = w10 * bx0;  tw[5] = w10 * ax;
    tw[6] = w11 * bx0;  tw[7] = w11 * ax;
}

__global__ void __launch_bounds__(256) elastic_kernel(
    float* __restrict__ out)           // [B,2,160,160,160]
{
    // block: 32 w x 8 ty, each thread does voxels (w, h) and (w, h+8).
    // grid: (5 w-tiles, 10 h-tiles * 160 d, 4 b)
    const int b  = blockIdx.z;
    const int d  = blockIdx.y / 10;
    const int ht = blockIdx.y % 10;
    const int tx = threadIdx.x;
    const int hA = ht * 16 + threadIdx.y;
    const int hB = hA + 8;
    const int w  = blockIdx.x * 32 + tx;

    // shared across both voxels (same w)
    const float s = 7.0f / 159.0f;
    const float cx  = w * s;
    const int   ix0 = (int)cx;
    const float fx  = cx - ix0;

    int baseA, baseB;
    float twA[8], twB[8];
    voxel_setup(b, d, hA, w, ix0, fx, baseA, twA);
    voxel_setup(b, d, hB, w, ix0, fx, baseB, twB);

    const __half2* __restrict__ xb = xh + (size_t)b * N3;

    // front-batch all 16 gather loads; constant tap offsets -> LDG immediates
    __half2 tA[8], tB[8];
    {
        const __half2* p = xb + baseA;
        tA[0] = __ldg(p);                      tA[1] = __ldg(p + 1);
        tA[2] = __ldg(p + DIMN);               tA[3] = __ldg(p + DIMN + 1);
        tA[4] = __ldg(p + DIMN*DIMN);          tA[5] = __ldg(p + DIMN*DIMN + 1);
        tA[6] = __ldg(p + DIMN*DIMN + DIMN);   tA[7] = __ldg(p + DIMN*DIMN + DIMN + 1);
    }
    {
        const __half2* p = xb + baseB;
        tB[0] = __ldg(p);                      tB[1] = __ldg(p + 1);
        tB[2] = __ldg(p + DIMN);               tB[3] = __ldg(p + DIMN + 1);
        tB[4] = __ldg(p + DIMN*DIMN);          tB[5] = __ldg(p + DIMN*DIMN + 1);
        tB[6] = __ldg(p + DIMN*DIMN + DIMN);   tB[7] = __ldg(p + DIMN*DIMN + DIMN + 1);
    }

    float vA0 = 0.f, vA1 = 0.f, vB0 = 0.f, vB1 = 0.f;
    #pragma unroll
    for (int k = 0; k < 8; k++) {
        const float2 fA = __half22float2(tA[k]);
        const float2 fB = __half22float2(tB[k]);
        vA0 = fmaf(twA[k], fA.x, vA0);
        vA1 = fmaf(twA[k], fA.y, vA1);
        vB0 = fmaf(twB[k], fB.x, vB0);
        vB1 = fmaf(twB[k], fB.y, vB1);
    }

    const int spatialA = (d * DIMN + hA) * DIMN + w;
    const int spatialB = spatialA + 8 * DIMN;
    float* __restrict__ o0 = out + (size_t)b * 2 * N3;
    o0[spatialA]      = vA0;
    o0[N3 + spatialA] = vA1;
    o0[spatialB]      = vB0;
    o0[N3 + spatialB] = vB1;
}

extern "C" void kernel_launch(void* const* d_in, const int* in_sizes, int n_in,
                              void* d_out, int out_size) {
    const float* x    = (const float*)d_in[0];
    const float* flow = (const float*)d_in[1];
    float* out        = (float*)d_out;

    dim3 pblock(256);
    dim3 pgrid(N3 / 1024, 5);          // y<4: interleave per batch; y==4: flow nodes
    prepass_kernel<<<pgrid, pblock>>>(x, flow);

    dim3 block(32, 8);                 // 256 threads, 2 voxels each
    dim3 grid(5, 10 * DIMN, 4);        // (w-tiles, h-tiles*d, b)
    elastic_kernel<<<grid, block>>>(out);
}